// round 8
// baseline (speedup 1.0000x reference)
#include <cuda_runtime.h>

#define RS2 0.7071067811865476f
#define TAU_V 0.05f

constexpr int SH  = 34;              // even, ≡2 mod 32
constexpr int SD  = 1090;            // even, ≡2 mod 32
constexpr int SH2 = 17;              // strides in float2 units
constexpr int SD2 = 545;
constexpr int TILE_F = 32 * SD;      // 34880 floats = 139520 B
constexpr int NTHREADS = 512;

// valid level-1 band-block slots (slot = d3*16 + h3*4 + w3, excluding lll octant)
__device__ __constant__ unsigned char VSLOT[56] = {
    2,3,6,7,8,9,10,11,12,13,14,15,18,19,22,23,
    24,25,26,27,28,29,30,31,32,33,34,35,36,37,38,39,
    40,41,42,43,44,45,46,47,48,49,50,51,52,53,54,55,
    56,57,58,59,60,61,62,63
};

extern __shared__ float smem[];

__device__ __forceinline__ float2 f2add(float2 a, float2 b) {
    return make_float2((a.x + b.x) * RS2, (a.y + b.y) * RS2);
}
__device__ __forceinline__ float2 f2sub(float2 a, float2 b) {
    return make_float2((a.x - b.x) * RS2, (a.y - b.y) * RS2);
}

// ---- h/d pass over pairs of adjacent w columns (float2), in place ----
// line length N along stride SLINE2; NA lines in 'a' dim (base stride SBASE2), NW2 w-pairs.
template<int N, int NA, int NW2, int SBASE2, int SLINE2, bool FWD>
__device__ __forceinline__ void pass_hd(float2* T2, int tid) {
    constexpr int NL = NA * NW2;
    if (NL >= NTHREADS || tid < NL) {
        int a = tid / NW2, wp = tid - a * NW2;     // NW2 power of two → shifts
        float2* p = T2 + a * SBASE2 + wp;
        float2 v[N];
#pragma unroll
        for (int k = 0; k < N; k++) v[k] = p[k * SLINE2];
#pragma unroll
        for (int i = 0; i < N / 2; i++) {
            if (FWD) {
                p[i * SLINE2]           = f2add(v[2*i], v[2*i+1]);
                p[(i + N/2) * SLINE2]   = f2sub(v[2*i], v[2*i+1]);
            } else {
                p[(2*i) * SLINE2]       = f2add(v[i], v[i + N/2]);
                p[(2*i + 1) * SLINE2]   = f2sub(v[i], v[i + N/2]);
            }
        }
    }
}

// ---- level-2 w pass: 16-long lines along w at (d,h) in [0,16)^2, all-float2 ----
template<bool FWD>
__device__ __forceinline__ void pass_w16(float2* T2, int tid) {
    if (tid < 256) {
        int d = tid >> 4, h = tid & 15;
        float2* p = T2 + d * SD2 + h * SH2;
        float2 q[8];
#pragma unroll
        for (int k = 0; k < 8; k++) q[k] = p[k];
        if (FWD) {
#pragma unroll
            for (int t = 0; t < 4; t++) {
                float2 lo, hi;
                lo.x = (q[2*t].x   + q[2*t].y)   * RS2;
                lo.y = (q[2*t+1].x + q[2*t+1].y) * RS2;
                hi.x = (q[2*t].x   - q[2*t].y)   * RS2;
                hi.y = (q[2*t+1].x - q[2*t+1].y) * RS2;
                p[t] = lo; p[4 + t] = hi;
            }
        } else {
#pragma unroll
            for (int t = 0; t < 4; t++) {
                float2 lo = q[t], hi = q[4 + t];
                p[2*t]     = make_float2((lo.x + hi.x) * RS2, (lo.x - hi.x) * RS2);
                p[2*t + 1] = make_float2((lo.y + hi.y) * RS2, (lo.y - hi.y) * RS2);
            }
        }
    }
}

// ---- 2D Haar pyramid fwd + soft-threshold + inv on v[64] in registers ----
__device__ __forceinline__ void pyramid(float* v) {
#pragma unroll
    for (int lev = 0; lev < 3; lev++) {
        const int S = 8 >> lev, H = S >> 1;
#pragma unroll
        for (int j = 0; j < S; j++) {
            float t[4], u[4];
#pragma unroll
            for (int i = 0; i < H; i++) {
                float a = v[(2*i)*8+j], b = v[(2*i+1)*8+j];
                t[i] = (a + b) * RS2; u[i] = (a - b) * RS2;
            }
#pragma unroll
            for (int i = 0; i < H; i++) { v[i*8+j] = t[i]; v[(i+H)*8+j] = u[i]; }
        }
#pragma unroll
        for (int i = 0; i < S; i++) {
            float t[4], u[4];
#pragma unroll
            for (int j = 0; j < H; j++) {
                float a = v[i*8+2*j], b = v[i*8+2*j+1];
                t[j] = (a + b) * RS2; u[j] = (a - b) * RS2;
            }
#pragma unroll
            for (int j = 0; j < H; j++) { v[i*8+j] = t[j]; v[i*8+j+H] = u[j]; }
        }
    }
#pragma unroll
    for (int e = 1; e < 64; e++)
        v[e] = copysignf(fmaxf(fabsf(v[e]) - TAU_V, 0.0f), v[e]);
#pragma unroll
    for (int lev = 2; lev >= 0; lev--) {
        const int S = 8 >> lev, H = S >> 1;
#pragma unroll
        for (int i = 0; i < S; i++) {
            float t[4], u[4];
#pragma unroll
            for (int j = 0; j < H; j++) {
                float lo = v[i*8+j], hi = v[i*8+j+H];
                t[j] = (lo + hi) * RS2; u[j] = (lo - hi) * RS2;
            }
#pragma unroll
            for (int j = 0; j < H; j++) { v[i*8+2*j] = t[j]; v[i*8+2*j+1] = u[j]; }
        }
#pragma unroll
        for (int j = 0; j < S; j++) {
            float t[4], u[4];
#pragma unroll
            for (int i = 0; i < H; i++) {
                float lo = v[i*8+j], hi = v[(i+H)*8+j];
                t[i] = (lo + hi) * RS2; u[i] = (lo - hi) * RS2;
            }
#pragma unroll
            for (int i = 0; i < H; i++) { v[(2*i)*8+j] = t[i]; v[(2*i+1)*8+j] = u[i]; }
        }
    }
}

// R4-style group: compute, then 3 ordered in-T writeback phases (n0 store, n1 +=, n2 merge/3).
// No trailing barrier — successive groups touch disjoint block regions.
// n0/n1 slice rows are float2-aligned (even strides, bw ≡ 0 mod 8); n2 is scalar (j-stride SH).
__device__ __forceinline__ void bandlet_group(float* T, int nrm, bool active,
                                              int bd, int bh, int bw, int s) {
    float v[64];
    if (active) {
        if (nrm == 0) {
            const float2* p = reinterpret_cast<const float2*>(T + (bd+s)*SD + bh*SH + bw);
#pragma unroll
            for (int i = 0; i < 8; i++)
#pragma unroll
                for (int jp = 0; jp < 4; jp++) {
                    float2 q = p[i*SH2 + jp];
                    v[i*8 + 2*jp] = q.x; v[i*8 + 2*jp + 1] = q.y;
                }
        } else if (nrm == 1) {
            const float2* p = reinterpret_cast<const float2*>(T + bd*SD + (bh+s)*SH + bw);
#pragma unroll
            for (int i = 0; i < 8; i++)
#pragma unroll
                for (int jp = 0; jp < 4; jp++) {
                    float2 q = p[i*SD2 + jp];
                    v[i*8 + 2*jp] = q.x; v[i*8 + 2*jp + 1] = q.y;
                }
        } else {
            const float* p = T + bd*SD + bh*SH + bw + s;
#pragma unroll
            for (int i = 0; i < 8; i++)
#pragma unroll
                for (int j = 0; j < 8; j++) v[i*8+j] = p[i*SD + j*SH];
        }
        pyramid(v);
    }
    __syncthreads();
    if (active && nrm == 0) {
        float2* p = reinterpret_cast<float2*>(T + (bd+s)*SD + bh*SH + bw);
#pragma unroll
        for (int i = 0; i < 8; i++)
#pragma unroll
            for (int jp = 0; jp < 4; jp++)
                p[i*SH2 + jp] = make_float2(v[i*8 + 2*jp], v[i*8 + 2*jp + 1]);
    }
    __syncthreads();
    if (active && nrm == 1) {
        float2* p = reinterpret_cast<float2*>(T + bd*SD + (bh+s)*SH + bw);
#pragma unroll
        for (int i = 0; i < 8; i++)
#pragma unroll
            for (int jp = 0; jp < 4; jp++) {
                float2 q = p[i*SD2 + jp];
                q.x += v[i*8 + 2*jp]; q.y += v[i*8 + 2*jp + 1];
                p[i*SD2 + jp] = q;
            }
    }
    __syncthreads();
    if (active && nrm == 2) {
        float* p = T + bd*SD + bh*SH + bw + s;
#pragma unroll
        for (int i = 0; i < 8; i++)
#pragma unroll
            for (int j = 0; j < 8; j++)
                p[i*SD + j*SH] = (p[i*SD + j*SH] + v[i*8+j]) * (1.0f / 3.0f);
    }
}

__global__ __launch_bounds__(NTHREADS, 1)
void bandlet3d_kernel(const float* __restrict__ x, float* __restrict__ y) {
    float* T = smem;
    float2* T2 = reinterpret_cast<float2*>(smem);
    const int tid = threadIdx.x;

    const int bc = blockIdx.x;
    const int batch = bc / 125;
    const int rem = bc - batch * 125;
    const int td = rem / 25;
    const int th = (rem / 5) % 5;
    const int tw = rem % 5;
    const long long gbase = (long long)batch * 4096000LL
                          + (long long)td * 32 * 25600 + th * 32 * 160 + tw * 32;

    // ---- fused coalesced load + level-1 w-transform (2 butterflies per float4) ----
    for (int l = tid; l < 8192; l += NTHREADS) {
        int w4 = l & 7, h = (l >> 3) & 31, d = l >> 8;     // w4 fastest → coalesced LDG.128
        float4 q = *reinterpret_cast<const float4*>(x + gbase + d*25600 + h*160 + w4*4);
        float2* p = T2 + d*SD2 + h*SH2;
        p[w4]     = make_float2((q.x + q.y) * RS2, (q.z + q.w) * RS2);   // lo at 2w4,2w4+1
        p[w4 + 8] = make_float2((q.x - q.y) * RS2, (q.z - q.w) * RS2);   // hi at +16
    }
    __syncthreads();

    // forward level-1 h and d (paired w columns)
    pass_hd<32, 32, 16, SD2, SH2, true>(T2, tid); __syncthreads();
    pass_hd<32, 32, 16, SH2, SD2, true>(T2, tid); __syncthreads();

    // ---- level-1 bandlet: 56 blocks in groups of 21/21/14 ----
    for (int g = 0; g < 3; g++) {
        const int base = g * 21;
        const int nblk = (g == 2) ? 14 : 21;
        const int ntask = nblk * 8;
        int nrm = 3, s = 0, bd = 0, bh = 0, bw = 0;
        bool active = (tid < 3 * ntask);
        if (active) {
            nrm = tid / ntask;
            int r = tid - nrm * ntask;
            int bg = r >> 3; s = r & 7;
            int slot = VSLOT[base + bg];
            bd = ((slot >> 4) & 3) * 8;
            bh = ((slot >> 2) & 3) * 8;
            bw = (slot & 3) * 8;
        }
        bandlet_group(T, nrm, active, bd, bh, bw, s);
    }
    // no barrier: fwd level-2 touches only the lll region (disjoint from band blocks)

    // forward level-2 (w, h, d on [0:16)^3)
    pass_w16<true>(T2, tid);                       __syncthreads();
    pass_hd<16, 16, 8, SD2, SH2, true>(T2, tid);   __syncthreads();
    pass_hd<16, 16, 8, SH2, SD2, true>(T2, tid);   __syncthreads();

    // ---- level-2 bandlet: 7 blocks, 168 tasks ----
    {
        int nrm = 3, s = 0, bd = 0, bh = 0, bw = 0;
        bool active = (tid < 168);
        if (active) {
            nrm = tid / 56;
            int r = tid - nrm * 56;
            int bg = r >> 3; s = r & 7;
            int slot = bg + 1;
            bd = ((slot >> 2) & 1) * 8;
            bh = ((slot >> 1) & 1) * 8;
            bw = (slot & 1) * 8;
        }
        bandlet_group(T, nrm, active, bd, bh, bw, s);
    }
    __syncthreads();   // idwt level-2 reads the band blocks just written

    // inverse level-2 (w, h, d)
    pass_w16<false>(T2, tid);                      __syncthreads();
    pass_hd<16, 16, 8, SD2, SH2, false>(T2, tid);  __syncthreads();
    pass_hd<16, 16, 8, SH2, SD2, false>(T2, tid);  __syncthreads();

    // inverse level-1: d, h, then w fused with the store (axis transforms commute)
    pass_hd<32, 32, 16, SH2, SD2, false>(T2, tid); __syncthreads();
    pass_hd<32, 32, 16, SD2, SH2, false>(T2, tid); __syncthreads();

    // ---- fused inverse level-1 w-transform + coalesced store ----
    for (int l = tid; l < 8192; l += NTHREADS) {
        int w4 = l & 7, h = (l >> 3) & 31, d = l >> 8;
        const float2* p = T2 + d*SD2 + h*SH2;
        float2 lo = p[w4], hi = p[w4 + 8];
        float4 q;
        q.x = (lo.x + hi.x) * RS2; q.y = (lo.x - hi.x) * RS2;
        q.z = (lo.y + hi.y) * RS2; q.w = (lo.y - hi.y) * RS2;
        *reinterpret_cast<float4*>(y + gbase + d*25600 + h*160 + w4*4) = q;
    }
}

extern "C" void kernel_launch(void* const* d_in, const int* in_sizes, int n_in,
                              void* d_out, int out_size) {
    const float* x = (const float*)d_in[0];
    float* y = (float*)d_out;
    (void)in_sizes; (void)n_in; (void)out_size;

    const size_t smem_bytes = (size_t)TILE_F * sizeof(float); // 139520 B
    cudaFuncSetAttribute(bandlet3d_kernel,
                         cudaFuncAttributeMaxDynamicSharedMemorySize, (int)smem_bytes);
    bandlet3d_kernel<<<250, NTHREADS, smem_bytes>>>(x, y);
}